// round 11
// baseline (speedup 1.0000x reference)
#include <cuda_runtime.h>
#include <cuda_bf16.h>
#include <cstdint>
#include <math.h>

#define Bn 8
#define Tn 2048
#define Cn 1024
#define Hn 128
#define BT (Bn * Tn)

// bf16 hi/lo scratch (device globals, no allocation)
__device__ __nv_bfloat16 g_Qh[BT * Hn], g_Ql[BT * Hn];
__device__ __nv_bfloat16 g_Kh[BT * Hn], g_Kl[BT * Hn];
__device__ __nv_bfloat16 g_Vh[BT * Hn], g_Vl[BT * Hn];
__device__ __nv_bfloat16 g_Wh[3 * Hn * Cn], g_Wl[3 * Hn * Cn];  // [o][n][k]
__device__ __nv_bfloat16 g_Xh[BT * Cn], g_Xl[BT * Cn];          // [m][k]

// ---------------- helpers ----------------
#define SWZ(x) ((x) ^ (((x) >> 3) & 0x70))

__device__ __forceinline__ uint32_t smem_u32(const void* p) {
    uint32_t a;
    asm("{ .reg .u64 t; cvta.to.shared.u64 t, %1; cvt.u32.u64 %0, t; }" : "=r"(a) : "l"(p));
    return a;
}
__device__ __forceinline__ uint32_t pack2(float lo, float hi) {
    uint32_t r;
    asm("cvt.rn.bf16x2.f32 %0, %1, %2;" : "=r"(r) : "f"(hi), "f"(lo));
    return r;
}
__device__ __forceinline__ void split2(float a, float b, uint32_t& h, uint32_t& l) {
    float ah = __bfloat162float(__float2bfloat16(a));
    float bh = __bfloat162float(__float2bfloat16(b));
    h = pack2(ah, bh);
    l = pack2(a - ah, b - bh);
}
__device__ __forceinline__ void ldsm4(uint32_t* r, uint32_t addr) {
    asm volatile("ldmatrix.sync.aligned.m8n8.x4.shared.b16 {%0,%1,%2,%3}, [%4];"
                 : "=r"(r[0]), "=r"(r[1]), "=r"(r[2]), "=r"(r[3]) : "r"(addr));
}
__device__ __forceinline__ void ldsm4t(uint32_t* r, uint32_t addr) {
    asm volatile("ldmatrix.sync.aligned.m8n8.x4.trans.shared.b16 {%0,%1,%2,%3}, [%4];"
                 : "=r"(r[0]), "=r"(r[1]), "=r"(r[2]), "=r"(r[3]) : "r"(addr));
}
__device__ __forceinline__ void mma_bf16(float* d, const uint32_t* a, uint32_t b0, uint32_t b1) {
    asm volatile("mma.sync.aligned.m16n8k16.row.col.f32.bf16.bf16.f32 "
                 "{%0,%1,%2,%3}, {%4,%5,%6,%7}, {%8,%9}, {%0,%1,%2,%3};"
                 : "+f"(d[0]), "+f"(d[1]), "+f"(d[2]), "+f"(d[3])
                 : "r"(a[0]), "r"(a[1]), "r"(a[2]), "r"(a[3]), "r"(b0), "r"(b1));
}
// A-operand 16x16 at (r0, bytecol) in a 128B-pitch tile
__device__ __forceinline__ uint32_t aAddr(uint32_t base, int r0, int bc, int lane) {
    int r = r0 + (lane & 15);
    int c = bc + ((lane >> 4) << 4);
    return base + SWZ((uint32_t)(r * 128 + c));
}
// B-operand x4 (two n8 tiles) from row-major B^T (n rows, k cols), 128B pitch
__device__ __forceinline__ uint32_t bAddr(uint32_t base, int n0, int bc, int lane) {
    int r = n0 + (lane & 7) + ((lane >> 4) << 3);
    int c = bc + (((lane >> 3) & 1) << 4);
    return base + SWZ((uint32_t)(r * 128 + c));
}
// B-operand x4 via trans from row-major V[k][n]: two 8K col-blocks (n>=64)
__device__ __forceinline__ uint32_t vAddr(uint32_t base, int n0, int k0, int lane) {
    int g = lane >> 3, li = lane & 7;
    int kr = k0 + ((g & 1) << 3) + li;
    int nc = n0 + ((g >> 1) << 3);
    return base + ((uint32_t)(nc >> 6) << 13) + SWZ((uint32_t)(kr * 128 + (nc & 63) * 2));
}
__device__ __forceinline__ void cpa16(uint32_t dst, const void* src) {
    asm volatile("cp.async.cg.shared.global [%0], [%1], 16;" :: "r"(dst), "l"(src));
}
#define CPA_COMMIT() asm volatile("cp.async.commit_group;" ::: "memory")
#define CPA_WAIT(n)  asm volatile("cp.async.wait_group %0;" :: "n"(n) : "memory")

// ============================================================================
// convW / convX
// ============================================================================
__global__ void convW(const float* __restrict__ Wq, const float* __restrict__ Wk,
                      const float* __restrict__ Wv) {
    int idx = blockIdx.x * 256 + threadIdx.x;
    int o = idx >> 17, rem = idx & 131071;
    int k = rem >> 7, n = rem & 127;
    const float* W = o == 0 ? Wq : o == 1 ? Wk : Wv;
    float f = W[(size_t)k * Hn + n];
    __nv_bfloat16 h = __float2bfloat16(f);
    size_t dst = ((size_t)o * Hn + n) * Cn + k;
    g_Wh[dst] = h;
    g_Wl[dst] = __float2bfloat16(f - __bfloat162float(h));
}
__global__ void convX(const float* __restrict__ x) {
    size_t idx = (size_t)blockIdx.x * 256 + threadIdx.x;   // over BT*Cn/2
    float2 v = *(const float2*)(x + 2 * idx);
    uint32_t h, l;
    split2(v.x, v.y, h, l);
    *(uint32_t*)((char*)g_Xh + 4 * idx) = h;
    *(uint32_t*)((char*)g_Xl + 4 * idx) = l;
}

// ============================================================================
// Projection: unchanged from R10 (grid (BT/128, 3), 512 thr, fused 3-product)
// ============================================================================
#define PJ_SMEM (131072 + 128)

__device__ __forceinline__ void pj_stage(uint32_t sb, int m0, int o, int kc, int tid) {
    uint32_t stg = sb + (uint32_t)(kc & 1) * 65536u;
    #pragma unroll
    for (int arr = 0; arr < 4; arr++) {
        const __nv_bfloat16* src =
            arr == 0 ? g_Xh : arr == 1 ? g_Xl : arr == 2 ? g_Wh : g_Wl;
        uint32_t dbase = stg + (uint32_t)arr * 16384u;
        #pragma unroll
        for (int i = 0; i < 2; i++) {
            int id = tid * 2 + i;                 // 0..1023
            int row = id >> 3, c = id & 7;        // 128 rows x 8 chunks
            size_t g = (arr < 2)
                ? ((size_t)(m0 + row) * Cn + kc * 64 + c * 8)
                : (((size_t)o * Hn + row) * Cn + kc * 64 + c * 8);
            cpa16(dbase + SWZ((uint32_t)(row * 128 + c * 16)), src + g);
        }
    }
}

__global__ __launch_bounds__(512, 1) void proj_mma(void) {
    extern __shared__ char smraw[];
    char* sm = (char*)(((uintptr_t)smraw + 127) & ~(uintptr_t)127);
    const uint32_t sb = smem_u32(sm);
    const int tid = threadIdx.x, lane = tid & 31, wid = tid >> 5;
    const int mw = wid >> 2, nww = wid & 3;
    const int m0 = blockIdx.x * 128, o = blockIdx.y;

    float d[2][4][4];
    #pragma unroll
    for (int i = 0; i < 2; i++)
        #pragma unroll
        for (int j = 0; j < 4; j++)
            #pragma unroll
            for (int e = 0; e < 4; e++) d[i][j][e] = 0.0f;

    pj_stage(sb, m0, o, 0, tid);
    CPA_COMMIT();

    for (int kc = 0; kc < 16; kc++) {
        if (kc + 1 < 16) { pj_stage(sb, m0, o, kc + 1, tid); CPA_COMMIT(); CPA_WAIT(1); }
        else CPA_WAIT(0);
        __syncthreads();

        const uint32_t stg = sb + (uint32_t)(kc & 1) * 65536u;
        #pragma unroll
        for (int kk = 0; kk < 4; kk++) {
            int bc = kk * 32;
            uint32_t aH[2][4], aL[2][4];
            #pragma unroll
            for (int mt = 0; mt < 2; mt++) {
                ldsm4(aH[mt], aAddr(stg, mw * 32 + mt * 16, bc, lane));
                ldsm4(aL[mt], aAddr(stg + 16384u, mw * 32 + mt * 16, bc, lane));
            }
            #pragma unroll
            for (int p2 = 0; p2 < 2; p2++) {
                uint32_t bH[4], bL[4];
                ldsm4(bH, bAddr(stg + 32768u, nww * 32 + p2 * 16, bc, lane));
                ldsm4(bL, bAddr(stg + 49152u, nww * 32 + p2 * 16, bc, lane));
                #pragma unroll
                for (int mt = 0; mt < 2; mt++) {
                    mma_bf16(d[mt][p2 * 2],     aH[mt], bH[0], bH[1]);
                    mma_bf16(d[mt][p2 * 2 + 1], aH[mt], bH[2], bH[3]);
                    mma_bf16(d[mt][p2 * 2],     aL[mt], bH[0], bH[1]);
                    mma_bf16(d[mt][p2 * 2 + 1], aL[mt], bH[2], bH[3]);
                    mma_bf16(d[mt][p2 * 2],     aH[mt], bL[0], bL[1]);
                    mma_bf16(d[mt][p2 * 2 + 1], aH[mt], bL[2], bL[3]);
                }
            }
        }
        __syncthreads();
    }

    __nv_bfloat16* oh = o == 0 ? g_Qh : o == 1 ? g_Kh : g_Vh;
    __nv_bfloat16* ol = o == 0 ? g_Ql : o == 1 ? g_Kl : g_Vl;
    #pragma unroll
    for (int mt = 0; mt < 2; mt++)
        #pragma unroll
        for (int h = 0; h < 2; h++) {
            int r = m0 + mw * 32 + mt * 16 + (lane >> 2) + h * 8;
            #pragma unroll
            for (int nt = 0; nt < 4; nt++) {
                int c = nww * 32 + nt * 8 + (lane & 3) * 2;
                uint32_t hw, lw;
                split2(d[mt][nt][h * 2], d[mt][nt][h * 2 + 1], hw, lw);
                size_t byt = ((size_t)r * Hn + c) * 2;
                *(uint32_t*)((char*)oh + byt) = hw;
                *(uint32_t*)((char*)ol + byt) = lw;
            }
        }
}

// ============================================================================
// Attention (FA2-style): 256 thr, 8 warps = 4 mw (16 q-rows) x 2 nw (32 keys).
// P never touches smem: S-frags -> softmax in regs -> A-frags for PV.
// O (16x128 fp32, 64 regs) and row-sums accumulate in registers across tiles;
// cross-nw reduction via smem once per segment. One barrier per tile.
// smem: QH 0 (2x8K halves), QL 16K | stages 32K,96K: {KH 0, KL 16K, VH 32K,
//       VL 48K} | Opart 160K (4x8K) | lpart 192K.
// ============================================================================
#define AT_STG0  32768
#define AT_OPART 163840
#define AT_LPART 196608
#define AT_SMEM  (196608 + 256 + 128)

__device__ __forceinline__ void at_stage(uint32_t sb, int b, int t, int s, int tid) {
    uint32_t stg = sb + AT_STG0 + (uint32_t)s * 65536u;
    #pragma unroll
    for (int arr = 0; arr < 4; arr++) {
        const __nv_bfloat16* src =
            arr == 0 ? g_Kh : arr == 1 ? g_Kl : arr == 2 ? g_Vh : g_Vl;
        uint32_t dbase = stg + (uint32_t)arr * 16384u;
        #pragma unroll
        for (int i = 0; i < 4; i++) {
            int id = tid * 4 + i;                 // 0..1023
            int row = id >> 4, c = id & 15;       // 64 rows x 16 chunks
            size_t g = (size_t)(b * Tn + t * 64 + row) * Hn + c * 8;
            uint32_t dst = dbase + ((c >= 8) ? 8192u : 0u)
                         + SWZ((uint32_t)(row * 128 + (c & 7) * 16));
            cpa16(dst, src + g);
        }
    }
}

__global__ __launch_bounds__(256, 1) void attn_mma(float* __restrict__ out) {
    extern __shared__ char smraw[];
    char* sm = (char*)(((uintptr_t)smraw + 127) & ~(uintptr_t)127);
    const uint32_t sb = smem_u32(sm);
    float* lpart = (float*)(sm + AT_LPART);
    const int tid = threadIdx.x, lane = tid & 31, wid = tid >> 5;
    const int mw = wid >> 1, nw = wid & 1;
    const int rq = lane >> 2, cq = (lane & 3) * 2;
    const int b = blockIdx.y;
    const int qt[2] = { (int)blockIdx.x, 31 - (int)blockIdx.x };

    const float scale = 0.08838834764831845f;  // 1/sqrt(128)

    at_stage(sb, b, 0, 0, tid);   // prefetch (seg0, tile0)
    CPA_COMMIT();

    int gi = 0;
    #pragma unroll 1
    for (int seg = 0; seg < 2; seg++) {
        const int q0 = qt[seg] * 64;
        const int nseg = qt[seg] + 1;

        // stage Q hi/lo (plain stores; safe: all warps past previous epilogue barrier)
        #pragma unroll
        for (int i = 0; i < 8; i++) {
            int id = tid * 8 + i;                 // 0..2047
            int arr = id >> 10, rem = id & 1023;
            int row = rem >> 4, c = rem & 15;
            int half = c >> 3;
            const __nv_bfloat16* src = (arr ? g_Ql : g_Qh);
            uint4 v = *(const uint4*)(src + (size_t)(b * Tn + q0 + row) * Hn + half * 64 + (c & 7) * 8);
            *(uint4*)(sm + arr * 16384 + half * 8192 + SWZ((uint32_t)(row * 128 + (c & 7) * 16))) = v;
        }

        float o[16][4];
        #pragma unroll
        for (int j = 0; j < 16; j++)
            #pragma unroll
            for (int e = 0; e < 4; e++) o[j][e] = 0.0f;
        float rs[2] = { 0.0f, 0.0f };

        #pragma unroll 1
        for (int t = 0; t < nseg; t++) {
            CPA_WAIT(0);           // this tile's stage complete (per-thread)
            __syncthreads();       // visibility of all threads' copies + WAR for buffer reuse
            if ((t + 1 < nseg) || (seg == 0)) {
                at_stage(sb, b, (t + 1 < nseg) ? t + 1 : 0, (gi + 1) & 1, tid);
                CPA_COMMIT();
            }
            const uint32_t stg = sb + AT_STG0 + (uint32_t)(gi & 1) * 65536u;

            // ---- S = Q K^T : 16 rows x 32 keys, 3 accumulator sets ----
            float shh[4][4], slh[4][4], shl[4][4];
            #pragma unroll
            for (int g = 0; g < 4; g++)
                #pragma unroll
                for (int e = 0; e < 4; e++) { shh[g][e] = 0.f; slh[g][e] = 0.f; shl[g][e] = 0.f; }

            #pragma unroll
            for (int kk = 0; kk < 8; kk++) {
                uint32_t hb = (uint32_t)(kk >> 2) * 8192u;
                int bc = (kk & 3) * 32;
                uint32_t aH[4], aL[4], bHa[4], bHb[4], bLa[4], bLb[4];
                ldsm4(aH,  aAddr(sb + hb,           mw * 16, bc, lane));
                ldsm4(aL,  aAddr(sb + 16384u + hb,  mw * 16, bc, lane));
                ldsm4(bHa, bAddr(stg + hb,          nw * 32,      bc, lane));
                ldsm4(bHb, bAddr(stg + hb,          nw * 32 + 16, bc, lane));
                ldsm4(bLa, bAddr(stg + 16384u + hb, nw * 32,      bc, lane));
                ldsm4(bLb, bAddr(stg + 16384u + hb, nw * 32 + 16, bc, lane));
                mma_bf16(shh[0], aH, bHa[0], bHa[1]);
                mma_bf16(shh[1], aH, bHa[2], bHa[3]);
                mma_bf16(shh[2], aH, bHb[0], bHb[1]);
                mma_bf16(shh[3], aH, bHb[2], bHb[3]);
                mma_bf16(slh[0], aL, bHa[0], bHa[1]);
                mma_bf16(slh[1], aL, bHa[2], bHa[3]);
                mma_bf16(slh[2], aL, bHb[0], bHb[1]);
                mma_bf16(slh[3], aL, bHb[2], bHb[3]);
                mma_bf16(shl[0], aH, bLa[0], bLa[1]);
                mma_bf16(shl[1], aH, bLa[2], bLa[3]);
                mma_bf16(shl[2], aH, bLb[0], bLb[1]);
                mma_bf16(shl[3], aH, bLb[2], bLb[3]);
            }

            // ---- softmax in registers (max-free) + register row-sums ----
            float pr[4][4];
            const int lim0 = q0 + mw * 16 + rq;
            const int lim1 = lim0 + 8;
            #pragma unroll
            for (int g = 0; g < 4; g++) {
                int j = t * 64 + nw * 32 + g * 8 + cq;
                float z0 = shh[g][0] + slh[g][0] + shl[g][0];
                float z1 = shh[g][1] + slh[g][1] + shl[g][1];
                float z2 = shh[g][2] + slh[g][2] + shl[g][2];
                float z3 = shh[g][3] + slh[g][3] + shl[g][3];
                float p0 = (j     <= lim0) ? __expf(z0 * scale) : 0.0f;
                float p1 = (j + 1 <= lim0) ? __expf(z1 * scale) : 0.0f;
                float p2 = (j     <= lim1) ? __expf(z2 * scale) : 0.0f;
                float p3 = (j + 1 <= lim1) ? __expf(z3 * scale) : 0.0f;
                pr[g][0] = p0; pr[g][1] = p1; pr[g][2] = p2; pr[g][3] = p3;
                rs[0] += p0 + p1;
                rs[1] += p2 + p3;
            }
            // pack P into A-fragments (hi/lo) — no smem round trip
            uint32_t aPh[2][4], aPl[2][4];
            #pragma unroll
            for (int kg = 0; kg < 2; kg++) {
                split2(pr[2 * kg][0],     pr[2 * kg][1],     aPh[kg][0], aPl[kg][0]);
                split2(pr[2 * kg][2],     pr[2 * kg][3],     aPh[kg][1], aPl[kg][1]);
                split2(pr[2 * kg + 1][0], pr[2 * kg + 1][1], aPh[kg][2], aPl[kg][2]);
                split2(pr[2 * kg + 1][2], pr[2 * kg + 1][3], aPh[kg][3], aPl[kg][3]);
            }

            // ---- O += P V over all 128 h-cols (O partial per nw warp) ----
            #pragma unroll
            for (int kg = 0; kg < 2; kg++) {
                #pragma unroll
                for (int hb = 0; hb < 8; hb++) {
                    uint32_t bH[4], bL[4];
                    ldsm4t(bH, vAddr(stg + 32768u, hb * 16, nw * 32 + kg * 16, lane));
                    ldsm4t(bL, vAddr(stg + 49152u, hb * 16, nw * 32 + kg * 16, lane));
                    mma_bf16(o[2 * hb],     aPh[kg], bH[0], bH[1]);
                    mma_bf16(o[2 * hb + 1], aPh[kg], bH[2], bH[3]);
                    mma_bf16(o[2 * hb],     aPl[kg], bH[0], bH[1]);
                    mma_bf16(o[2 * hb + 1], aPl[kg], bH[2], bH[3]);
                    mma_bf16(o[2 * hb],     aPh[kg], bL[0], bL[1]);
                    mma_bf16(o[2 * hb + 1], aPh[kg], bL[2], bL[3]);
                }
            }
            gi++;
        }

        // ---- segment epilogue: reduce row-sums + O across nw, write out ----
        float r0 = rs[0];
        r0 += __shfl_xor_sync(0xffffffffu, r0, 1);
        r0 += __shfl_xor_sync(0xffffffffu, r0, 2);
        float r1 = rs[1];
        r1 += __shfl_xor_sync(0xffffffffu, r1, 1);
        r1 += __shfl_xor_sync(0xffffffffu, r1, 2);

        float* opart = (float*)(sm + AT_OPART + mw * 8192);
        if (nw == 1) {
            #pragma unroll
            for (int j = 0; j < 16; j++) {
                int col = (j >> 1) * 16 + (j & 1) * 8 + cq;
                *(float2*)(opart + rq * 128 + col)       = make_float2(o[j][0], o[j][1]);
                *(float2*)(opart + (rq + 8) * 128 + col) = make_float2(o[j][2], o[j][3]);
            }
            if ((lane & 3) == 0) {
                lpart[mw * 16 + rq] = r0;
                lpart[mw * 16 + rq + 8] = r1;
            }
        }
        __syncthreads();
        if (nw == 0) {
            float inv0 = 1.0f / (r0 + lpart[mw * 16 + rq]);
            float inv1 = 1.0f / (r1 + lpart[mw * 16 + rq + 8]);
            float* op = out + ((size_t)(b * Tn + q0 + mw * 16)) * Hn;
            #pragma unroll
            for (int j = 0; j < 16; j++) {
                int col = (j >> 1) * 16 + (j & 1) * 8 + cq;
                float2 q0v = *(float2*)(opart + rq * 128 + col);
                float2 q1v = *(float2*)(opart + (rq + 8) * 128 + col);
                *(float2*)(op + (size_t)rq * Hn + col) =
                    make_float2((o[j][0] + q0v.x) * inv0, (o[j][1] + q0v.y) * inv0);
                *(float2*)(op + (size_t)(rq + 8) * Hn + col) =
                    make_float2((o[j][2] + q1v.x) * inv1, (o[j][3] + q1v.y) * inv1);
            }
        }
        __syncthreads();   // Opart/lpart free before next segment reuses them
    }
}

extern "C" void kernel_launch(void* const* d_in, const int* in_sizes, int n_in,
                              void* d_out, int out_size)
{
    const float* x  = (const float*)d_in[0];
    const float* Wq = (const float*)d_in[1];
    const float* Wk = (const float*)d_in[2];
    const float* Wv = (const float*)d_in[3];
    float* out = (float*)d_out;

    cudaFuncSetAttribute(proj_mma, cudaFuncAttributeMaxDynamicSharedMemorySize, PJ_SMEM);
    cudaFuncSetAttribute(attn_mma, cudaFuncAttributeMaxDynamicSharedMemorySize, AT_SMEM);

    convW<<<1536, 256>>>(Wq, Wk, Wv);
    convX<<<BT * Cn / 512, 256>>>(x);
    proj_mma<<<dim3(BT / 128, 3), 512, PJ_SMEM>>>();
    attn_mma<<<dim3(Tn / 128, Bn), 256, AT_SMEM>>>(out);
}